// round 1
// baseline (speedup 1.0000x reference)
#include <cuda_runtime.h>

#define NN 8192      // nodes
#define F  512       // features (in == out)

// Scratch (device globals — no allocation allowed)
__device__ float g_dinv[NN];
__device__ float g_hs[(size_t)NN * F];   // dinv[j] * (x @ w)[j,f]

// ---------------------------------------------------------------------------
// Kernel 1: deg[i] = sum_j graph[j,i]  (column sums), dinv = deg^{-1/2}
// Coalesced: adjacent threads read adjacent columns of each row.
// ---------------------------------------------------------------------------
__global__ void deg_kernel(const float* __restrict__ graph) {
    int i = blockIdx.x * blockDim.x + threadIdx.x;
    float s0 = 0.f, s1 = 0.f, s2 = 0.f, s3 = 0.f;
    #pragma unroll 2
    for (int j = 0; j < NN; j += 4) {
        s0 += graph[(size_t)(j + 0) * NN + i];
        s1 += graph[(size_t)(j + 1) * NN + i];
        s2 += graph[(size_t)(j + 2) * NN + i];
        s3 += graph[(size_t)(j + 3) * NN + i];
    }
    g_dinv[i] = rsqrtf((s0 + s1) + (s2 + s3));
}

// ---------------------------------------------------------------------------
// Kernel 2: hs[m,f] = dinv[m] * sum_k x[m,k] * w[k,f]
// 64x64 tile, BK=16, 256 threads, 4x4 per thread.
// ---------------------------------------------------------------------------
__global__ __launch_bounds__(256) void xw_kernel(const float* __restrict__ x,
                                                 const float* __restrict__ w) {
    __shared__ float Xs[16][68];   // [k][m], padded so float4 rows stay 16B aligned
    __shared__ float Ws[16][64];   // [k][n]

    int tid = threadIdx.x;
    int tx = tid & 15;             // n-tile coord
    int ty = tid >> 4;             // m-tile coord
    int mBase = blockIdx.y * 64;
    int nBase = blockIdx.x * 64;

    float acc[4][4] = {};

    for (int k0 = 0; k0 < F; k0 += 16) {
        // Global -> regs
        int xm = tid >> 2;               // 0..63
        int xk = (tid & 3) * 4;          // 0..12
        float4 xv = *(const float4*)&x[(size_t)(mBase + xm) * F + k0 + xk];
        int wk = tid >> 4;               // 0..15
        int wn = (tid & 15) * 4;         // 0..60
        float4 wv = *(const float4*)&w[(size_t)(k0 + wk) * F + nBase + wn];

        __syncthreads();                 // previous tile's compute done
        Xs[xk + 0][xm] = xv.x;
        Xs[xk + 1][xm] = xv.y;
        Xs[xk + 2][xm] = xv.z;
        Xs[xk + 3][xm] = xv.w;
        *(float4*)&Ws[wk][wn] = wv;
        __syncthreads();

        #pragma unroll
        for (int kk = 0; kk < 16; kk++) {
            float4 a = *(const float4*)&Xs[kk][ty * 4];
            float4 b = *(const float4*)&Ws[kk][tx * 4];
            float ar[4] = {a.x, a.y, a.z, a.w};
            float br[4] = {b.x, b.y, b.z, b.w};
            #pragma unroll
            for (int r = 0; r < 4; r++)
                #pragma unroll
                for (int c = 0; c < 4; c++)
                    acc[r][c] = fmaf(ar[r], br[c], acc[r][c]);
        }
    }

    // Epilogue: scale by dinv[m], store to g_hs
    #pragma unroll
    for (int r = 0; r < 4; r++) {
        int m = mBase + ty * 4 + r;
        float d = g_dinv[m];
        float4 o;
        o.x = d * acc[r][0];
        o.y = d * acc[r][1];
        o.z = d * acc[r][2];
        o.w = d * acc[r][3];
        *(float4*)&g_hs[(size_t)m * F + nBase + tx * 4] = o;
    }
}

// ---------------------------------------------------------------------------
// Kernel 3: y[i,f] = dinv[i] * sum_j graph[j,i] * hs[j,f] + bias[f]
// C = G^T * HS, both operands K-major (K = j = rows). 128x128 tile, BK=16,
// 256 threads, 8x8 per thread.
// ---------------------------------------------------------------------------
__global__ __launch_bounds__(256) void agg_kernel(const float* __restrict__ graph,
                                                  const float* __restrict__ bias,
                                                  float* __restrict__ y) {
    __shared__ float Gs[16][128];  // [j][i]  — loaded directly, no transpose
    __shared__ float Hs[16][128];  // [j][f]

    int tid = threadIdx.x;
    int tx = tid & 15;             // f-tile coord (8 cols each)
    int ty = tid >> 4;             // i-tile coord (8 rows each)
    int iBase = blockIdx.y * 128;
    int fBase = blockIdx.x * 128;

    // Load mapping: 2048 floats per tile, 8 consecutive per thread
    int lr = (tid * 8) >> 7;       // row within tile (0..15)
    int lc = (tid * 8) & 127;      // col within tile (multiple of 8)

    float acc[8][8] = {};

    for (int k0 = 0; k0 < NN; k0 += 16) {
        const float* gp = &graph[(size_t)(k0 + lr) * NN + iBase + lc];
        const float* hp = &g_hs[(size_t)(k0 + lr) * F + fBase + lc];
        float4 g0 = *(const float4*)(gp);
        float4 g1 = *(const float4*)(gp + 4);
        float4 h0 = *(const float4*)(hp);
        float4 h1 = *(const float4*)(hp + 4);

        __syncthreads();           // previous tile's compute done
        *(float4*)&Gs[lr][lc]     = g0;
        *(float4*)&Gs[lr][lc + 4] = g1;
        *(float4*)&Hs[lr][lc]     = h0;
        *(float4*)&Hs[lr][lc + 4] = h1;
        __syncthreads();

        #pragma unroll
        for (int kk = 0; kk < 16; kk++) {
            float4 a0 = *(const float4*)&Gs[kk][ty * 8];
            float4 a1 = *(const float4*)&Gs[kk][ty * 8 + 4];
            float4 b0 = *(const float4*)&Hs[kk][tx * 8];
            float4 b1 = *(const float4*)&Hs[kk][tx * 8 + 4];
            float ar[8] = {a0.x, a0.y, a0.z, a0.w, a1.x, a1.y, a1.z, a1.w};
            float br[8] = {b0.x, b0.y, b0.z, b0.w, b1.x, b1.y, b1.z, b1.w};
            #pragma unroll
            for (int r = 0; r < 8; r++)
                #pragma unroll
                for (int c = 0; c < 8; c++)
                    acc[r][c] = fmaf(ar[r], br[c], acc[r][c]);
        }
    }

    // Epilogue: y = dinv[i]*acc + bias[f]
    float4 bv0 = *(const float4*)&bias[fBase + tx * 8];
    float4 bv1 = *(const float4*)&bias[fBase + tx * 8 + 4];
    float bb[8] = {bv0.x, bv0.y, bv0.z, bv0.w, bv1.x, bv1.y, bv1.z, bv1.w};
    #pragma unroll
    for (int r = 0; r < 8; r++) {
        int i = iBase + ty * 8 + r;
        float d = g_dinv[i];
        float4 o0, o1;
        o0.x = fmaf(d, acc[r][0], bb[0]);
        o0.y = fmaf(d, acc[r][1], bb[1]);
        o0.z = fmaf(d, acc[r][2], bb[2]);
        o0.w = fmaf(d, acc[r][3], bb[3]);
        o1.x = fmaf(d, acc[r][4], bb[4]);
        o1.y = fmaf(d, acc[r][5], bb[5]);
        o1.z = fmaf(d, acc[r][6], bb[6]);
        o1.w = fmaf(d, acc[r][7], bb[7]);
        float* yp = &y[(size_t)i * F + fBase + tx * 8];
        *(float4*)(yp)     = o0;
        *(float4*)(yp + 4) = o1;
    }
}

// ---------------------------------------------------------------------------
extern "C" void kernel_launch(void* const* d_in, const int* in_sizes, int n_in,
                              void* d_out, int out_size) {
    const float* x      = (const float*)d_in[0];  // [8192, 512]
    const float* graph  = (const float*)d_in[1];  // [8192, 8192]
    const float* weight = (const float*)d_in[2];  // [512, 512]
    const float* bias   = (const float*)d_in[3];  // [512]
    float* y = (float*)d_out;                     // [8192, 512]

    deg_kernel<<<NN / 256, 256>>>(graph);
    xw_kernel<<<dim3(F / 64, NN / 64), 256>>>(x, weight);
    agg_kernel<<<dim3(F / 128, NN / 128), 256>>>(graph, bias, y);
}

// round 3
// speedup vs baseline: 3.9364x; 3.9364x over previous
#include <cuda_runtime.h>
#include <cstdint>

#define NN 8192
#define F  512

// ------------------------- device scratch (no allocs allowed) ---------------
__device__ float g_deg[NN];
__device__ float g_dinv[NN];
__device__ float g_hs[(size_t)NN * F];   // dinv[m] * (x @ w)[m,f], row-major [m][f]

// ------------------------- helpers ------------------------------------------
__device__ __forceinline__ uint32_t smem_u32(const void* p) {
    uint32_t a;
    asm("{ .reg .u64 t; cvta.to.shared.u64 t, %1; cvt.u32.u64 %0, t; }"
        : "=r"(a) : "l"(p));
    return a;
}
__device__ __forceinline__ uint32_t f2tf(float x) {   // unbiased f32 -> tf32
    uint32_t r;
    asm("cvt.rna.tf32.f32 %0, %1;" : "=r"(r) : "f"(x));
    return r;
}
__device__ __forceinline__ void mma_tf32(float* c, const uint32_t* a, const uint32_t* b) {
    asm volatile(
        "mma.sync.aligned.m16n8k8.row.col.f32.tf32.tf32.f32 "
        "{%0,%1,%2,%3}, {%4,%5,%6,%7}, {%8,%9}, {%0,%1,%2,%3};"
        : "+f"(c[0]), "+f"(c[1]), "+f"(c[2]), "+f"(c[3])
        : "r"(a[0]), "r"(a[1]), "r"(a[2]), "r"(a[3]), "r"(b[0]), "r"(b[1]));
}
__device__ __forceinline__ void cpa16(uint32_t dst, const void* src) {
    asm volatile("cp.async.cg.shared.global [%0], [%1], 16;" :: "r"(dst), "l"(src));
}

// ------------------------- kernel 0/1/2: degree -----------------------------
__global__ void zero_deg_kernel() {
    g_deg[blockIdx.x * 256 + threadIdx.x] = 0.f;
}

// deg[i] = sum_j graph[j][i]; split over j (grid.y), coalesced along i.
__global__ __launch_bounds__(256) void deg_kernel(const float* __restrict__ g) {
    int i4 = blockIdx.x * 1024 + threadIdx.x * 4;   // grid.x = 8
    int j0 = blockIdx.y * 256;                      // grid.y = 32
    float s0 = 0.f, s1 = 0.f, s2 = 0.f, s3 = 0.f;
    #pragma unroll 4
    for (int j = 0; j < 256; j++) {
        float4 v = *(const float4*)&g[(size_t)(j0 + j) * NN + i4];
        s0 += v.x; s1 += v.y; s2 += v.z; s3 += v.w;
    }
    atomicAdd(&g_deg[i4 + 0], s0);
    atomicAdd(&g_deg[i4 + 1], s1);
    atomicAdd(&g_deg[i4 + 2], s2);
    atomicAdd(&g_deg[i4 + 3], s3);
}

__global__ void dinv_kernel() {
    int i = blockIdx.x * 256 + threadIdx.x;
    g_dinv[i] = rsqrtf(g_deg[i]);
}

// ------------------------- kernel 3: hs = diag(dinv) * (X @ W) --------------
// M=8192 N=512 K=512, tf32 mma.sync. BM=128 BN=128 BK=16, 256 thr, 8 warps.
// Warp tile 32(M) x 64(N).
#define XSA 136   // smem A row stride (mod 32 == 8 -> conflict-free frags)
#define XSB 136
__global__ __launch_bounds__(256) void xw_tc(const float* __restrict__ x,
                                             const float* __restrict__ w) {
    __shared__ float As[16 * XSA];   // [k][m]
    __shared__ float Bs[16 * XSB];   // [k][n]

    int tid = threadIdx.x;
    int wid = tid >> 5, lane = tid & 31;
    int g = lane >> 2, tg = lane & 3;
    int wm = wid >> 1, wn = wid & 1;
    int mBase = blockIdx.y * 128;
    int nBase = blockIdx.x * 128;

    float acc[2][8][4] = {};
    float4 av[2], bv[2];
    int am[2], ak[2], br[2], bc[2];
    #pragma unroll
    for (int q = 0; q < 2; q++) {
        int id = tid + 256 * q;
        am[q] = id >> 2; ak[q] = (id & 3) * 4;       // A: 128 rows x 4 k-chunks
        br[q] = id >> 5; bc[q] = (id & 31) * 4;      // B: 16 rows x 32 f4
    }

    auto gload = [&](int kt) {
        int k0 = kt * 16;
        #pragma unroll
        for (int q = 0; q < 2; q++) {
            av[q] = *(const float4*)&x[(size_t)(mBase + am[q]) * F + k0 + ak[q]];
            bv[q] = *(const float4*)&w[(size_t)(k0 + br[q]) * F + nBase + bc[q]];
        }
    };

    gload(0);
    for (int kt = 0; kt < F / 16; kt++) {
        __syncthreads();
        #pragma unroll
        for (int q = 0; q < 2; q++) {
            As[(ak[q] + 0) * XSA + am[q]] = av[q].x;   // transpose into [k][m]
            As[(ak[q] + 1) * XSA + am[q]] = av[q].y;
            As[(ak[q] + 2) * XSA + am[q]] = av[q].z;
            As[(ak[q] + 3) * XSA + am[q]] = av[q].w;
            *(float4*)&Bs[br[q] * XSB + bc[q]] = bv[q];
        }
        __syncthreads();
        if (kt + 1 < F / 16) gload(kt + 1);

        #pragma unroll
        for (int ks = 0; ks < 2; ks++) {
            int kb = ks * 8;
            uint32_t af[2][4], bf[8][2];
            #pragma unroll
            for (int mt = 0; mt < 2; mt++) {
                int m = wm * 32 + mt * 16 + g;
                af[mt][0] = f2tf(As[(kb + tg) * XSA + m]);
                af[mt][1] = f2tf(As[(kb + tg) * XSA + m + 8]);
                af[mt][2] = f2tf(As[(kb + tg + 4) * XSA + m]);
                af[mt][3] = f2tf(As[(kb + tg + 4) * XSA + m + 8]);
            }
            #pragma unroll
            for (int nt = 0; nt < 8; nt++) {
                int n = wn * 64 + nt * 8 + g;
                bf[nt][0] = f2tf(Bs[(kb + tg) * XSB + n]);
                bf[nt][1] = f2tf(Bs[(kb + tg + 4) * XSB + n]);
            }
            #pragma unroll
            for (int mt = 0; mt < 2; mt++)
                #pragma unroll
                for (int nt = 0; nt < 8; nt++)
                    mma_tf32(acc[mt][nt], af[mt], bf[nt]);
        }
    }

    #pragma unroll
    for (int mt = 0; mt < 2; mt++) {
        int r0 = mBase + wm * 32 + mt * 16 + g;
        float d0 = g_dinv[r0], d1 = g_dinv[r0 + 8];
        #pragma unroll
        for (int nt = 0; nt < 8; nt++) {
            int c = nBase + wn * 64 + nt * 8 + tg * 2;
            float2 o0 = {d0 * acc[mt][nt][0], d0 * acc[mt][nt][1]};
            float2 o1 = {d1 * acc[mt][nt][2], d1 * acc[mt][nt][3]};
            *(float2*)&g_hs[(size_t)r0 * F + c] = o0;
            *(float2*)&g_hs[(size_t)(r0 + 8) * F + c] = o1;
        }
    }
}

// ------------------------- kernel 4: aggregation ----------------------------
// y[i,f] = dinv[i] * sum_j G[j,i]*hs[j,f] + bias[f]
// A = G^T (K-major in gmem), B = hs (K-major in gmem): both coalesced.
// BM=128 BN=256 BK=16, 512 threads (16 warps, 4x4), warp tile 32x64.
// 3-stage cp.async pipeline.
#define ASA 136
#define ASB 264
#define A_FLOATS (16 * ASA)              // 2176
#define STG_FLOATS (16 * ASA + 16 * ASB) // 6400
#define STAGES 3
#define KT (NN / 16)                     // 512

__global__ __launch_bounds__(512, 1) void agg_tc(const float* __restrict__ graph,
                                                 const float* __restrict__ bias,
                                                 float* __restrict__ y) {
    extern __shared__ float dsm[];
    uint32_t sbase = smem_u32(dsm);

    int tid = threadIdx.x;
    int wid = tid >> 5, lane = tid & 31;
    int g = lane >> 2, tg = lane & 3;
    int wm = wid >> 2, wn = wid & 3;     // 4x4 warps
    int iBase = blockIdx.y * 128;
    int fBase = blockIdx.x * 256;

    // load maps
    int a_row = tid >> 5, a_c4 = (tid & 31) * 4;          // A: 16x32 f4, 1/thread
    int b_row[2], b_c4[2];                                 // B: 16x64 f4, 2/thread
    #pragma unroll
    for (int q = 0; q < 2; q++) {
        int id = tid + 512 * q;
        b_row[q] = id >> 6; b_c4[q] = (id & 63) * 4;
    }

    const float* gA = graph + iBase;            // + j*NN + i
    const float* hB = g_hs + fBase;             // + j*F + f

    auto load_stage = [&](int it) {
        uint32_t sb = sbase + (uint32_t)(it % STAGES) * (STG_FLOATS * 4);
        int k0 = it * 16;
        cpa16(sb + (uint32_t)(a_row * ASA + a_c4) * 4,
              gA + (size_t)(k0 + a_row) * NN + a_c4);
        #pragma unroll
        for (int q = 0; q < 2; q++)
            cpa16(sb + (uint32_t)(A_FLOATS + b_row[q] * ASB + b_c4[q]) * 4,
                  hB + (size_t)(k0 + b_row[q]) * F + b_c4[q]);
    };

    float acc[2][8][4] = {};

    load_stage(0);
    asm volatile("cp.async.commit_group;" ::: "memory");
    load_stage(1);
    asm volatile("cp.async.commit_group;" ::: "memory");

    for (int it = 0; it < KT; it++) {
        if (it + 2 < KT) load_stage(it + 2);
        asm volatile("cp.async.commit_group;" ::: "memory");
        asm volatile("cp.async.wait_group 2;" ::: "memory");
        __syncthreads();

        const float* As = dsm + (it % STAGES) * STG_FLOATS;
        const float* Bs = As + A_FLOATS;

        #pragma unroll
        for (int ks = 0; ks < 2; ks++) {
            int kb = ks * 8;
            uint32_t af[2][4], bf[8][2];
            #pragma unroll
            for (int mt = 0; mt < 2; mt++) {
                int m = wm * 32 + mt * 16 + g;
                af[mt][0] = f2tf(As[(kb + tg) * ASA + m]);
                af[mt][1] = f2tf(As[(kb + tg) * ASA + m + 8]);
                af[mt][2] = f2tf(As[(kb + tg + 4) * ASA + m]);
                af[mt][3] = f2tf(As[(kb + tg + 4) * ASA + m + 8]);
            }
            #pragma unroll
            for (int nt = 0; nt < 8; nt++) {
                int n = wn * 64 + nt * 8 + g;
                bf[nt][0] = f2tf(Bs[(kb + tg) * ASB + n]);
                bf[nt][1] = f2tf(Bs[(kb + tg + 4) * ASB + n]);
            }
            #pragma unroll
            for (int mt = 0; mt < 2; mt++)
                #pragma unroll
                for (int nt = 0; nt < 8; nt++)
                    mma_tf32(acc[mt][nt], af[mt], bf[nt]);
        }
        __syncthreads();
    }

    // epilogue: y = dinv[i]*acc + bias[f]
    #pragma unroll
    for (int mt = 0; mt < 2; mt++) {
        int r0 = iBase + wm * 32 + mt * 16 + g;
        float d0 = g_dinv[r0], d1 = g_dinv[r0 + 8];
        #pragma unroll
        for (int nt = 0; nt < 8; nt++) {
            int c = fBase + wn * 64 + nt * 8 + tg * 2;
            float2 bb = *(const float2*)&bias[c];
            float2 o0, o1;
            o0.x = fmaf(d0, acc[mt][nt][0], bb.x);
            o0.y = fmaf(d0, acc[mt][nt][1], bb.y);
            o1.x = fmaf(d1, acc[mt][nt][2], bb.x);
            o1.y = fmaf(d1, acc[mt][nt][3], bb.y);
            *(float2*)&y[(size_t)r0 * F + c] = o0;
            *(float2*)&y[(size_t)(r0 + 8) * F + c] = o1;
        }
    }
}

// ---------------------------------------------------------------------------
extern "C" void kernel_launch(void* const* d_in, const int* in_sizes, int n_in,
                              void* d_out, int out_size) {
    const float* x      = (const float*)d_in[0];  // [8192, 512]
    const float* graph  = (const float*)d_in[1];  // [8192, 8192]
    const float* weight = (const float*)d_in[2];  // [512, 512]
    const float* bias   = (const float*)d_in[3];  // [512]
    float* y = (float*)d_out;                     // [8192, 512]

    cudaFuncSetAttribute(agg_tc, cudaFuncAttributeMaxDynamicSharedMemorySize,
                         STAGES * STG_FLOATS * 4);

    zero_deg_kernel<<<NN / 256, 256>>>();
    deg_kernel<<<dim3(8, 32), 256>>>(graph);
    dinv_kernel<<<NN / 256, 256>>>();
    xw_tc<<<dim3(F / 128, NN / 128), 256>>>(x, weight);
    agg_tc<<<dim3(F / 256, NN / 128), 512, STAGES * STG_FLOATS * 4>>>(graph, bias, y);
}

// round 4
// speedup vs baseline: 4.7512x; 1.2070x over previous
#include <cuda_runtime.h>
#include <cstdint>

#define NN 8192
#define F  512

// ------------------------- device scratch (no allocs allowed) ---------------
__device__ float g_deg[NN];
__device__ float g_dinv[NN];
__device__ float g_hs[(size_t)NN * F];   // dinv[m]*(XW)[m,f], tf32-rounded bits

// ------------------------- helpers ------------------------------------------
__device__ __forceinline__ uint32_t smem_u32(const void* p) {
    uint32_t a;
    asm("{ .reg .u64 t; cvta.to.shared.u64 t, %1; cvt.u32.u64 %0, t; }"
        : "=r"(a) : "l"(p));
    return a;
}
__device__ __forceinline__ uint32_t f2tf(float x) {   // unbiased f32 -> tf32
    uint32_t r;
    asm("cvt.rna.tf32.f32 %0, %1;" : "=r"(r) : "f"(x));
    return r;
}
__device__ __forceinline__ void mma_tf32(float* c, const uint32_t* a, const uint32_t* b) {
    asm volatile(
        "mma.sync.aligned.m16n8k8.row.col.f32.tf32.tf32.f32 "
        "{%0,%1,%2,%3}, {%4,%5,%6,%7}, {%8,%9}, {%0,%1,%2,%3};"
        : "+f"(c[0]), "+f"(c[1]), "+f"(c[2]), "+f"(c[3])
        : "r"(a[0]), "r"(a[1]), "r"(a[2]), "r"(a[3]), "r"(b[0]), "r"(b[1]));
}
__device__ __forceinline__ void cpa16(uint32_t dst, const void* src) {
    asm volatile("cp.async.cg.shared.global [%0], [%1], 16;" :: "r"(dst), "l"(src));
}

// ------------------------- degree pipeline ----------------------------------
__global__ void zero_deg_kernel() {
    g_deg[blockIdx.x * 256 + threadIdx.x] = 0.f;
}

// deg[i] = sum_j graph[j][i]; split over j (grid.y), coalesced along i.
__global__ __launch_bounds__(256) void deg_kernel(const float* __restrict__ g) {
    int i4 = blockIdx.x * 1024 + threadIdx.x * 4;   // grid.x = 8
    int j0 = blockIdx.y * 128;                      // grid.y = 64
    float s0 = 0.f, s1 = 0.f, s2 = 0.f, s3 = 0.f;
    #pragma unroll 4
    for (int j = 0; j < 128; j++) {
        float4 v = *(const float4*)&g[(size_t)(j0 + j) * NN + i4];
        s0 += v.x; s1 += v.y; s2 += v.z; s3 += v.w;
    }
    atomicAdd(&g_deg[i4 + 0], s0);
    atomicAdd(&g_deg[i4 + 1], s1);
    atomicAdd(&g_deg[i4 + 2], s2);
    atomicAdd(&g_deg[i4 + 3], s3);
}

__global__ void dinv_kernel() {
    int i = blockIdx.x * 256 + threadIdx.x;
    g_dinv[i] = rsqrtf(g_deg[i]);
}

// ------------------------- kernel 3: hs = diag(dinv) * (X @ W) --------------
// Output stored pre-rounded to tf32 (rna) so agg consumes it without CVT.
#define XSA 136
#define XSB 136
__global__ __launch_bounds__(256) void xw_tc(const float* __restrict__ x,
                                             const float* __restrict__ w) {
    __shared__ float As[16 * XSA];   // [k][m]
    __shared__ float Bs[16 * XSB];   // [k][n]

    int tid = threadIdx.x;
    int wid = tid >> 5, lane = tid & 31;
    int g = lane >> 2, tg = lane & 3;
    int wm = wid >> 1, wn = wid & 1;
    int mBase = blockIdx.y * 128;
    int nBase = blockIdx.x * 128;

    float acc[2][8][4] = {};
    float4 av[2], bv[2];
    int am[2], ak[2], br[2], bc[2];
    #pragma unroll
    for (int q = 0; q < 2; q++) {
        int id = tid + 256 * q;
        am[q] = id >> 2; ak[q] = (id & 3) * 4;
        br[q] = id >> 5; bc[q] = (id & 31) * 4;
    }

    auto gload = [&](int kt) {
        int k0 = kt * 16;
        #pragma unroll
        for (int q = 0; q < 2; q++) {
            av[q] = *(const float4*)&x[(size_t)(mBase + am[q]) * F + k0 + ak[q]];
            bv[q] = *(const float4*)&w[(size_t)(k0 + br[q]) * F + nBase + bc[q]];
        }
    };

    gload(0);
    for (int kt = 0; kt < F / 16; kt++) {
        __syncthreads();
        #pragma unroll
        for (int q = 0; q < 2; q++) {
            As[(ak[q] + 0) * XSA + am[q]] = av[q].x;
            As[(ak[q] + 1) * XSA + am[q]] = av[q].y;
            As[(ak[q] + 2) * XSA + am[q]] = av[q].z;
            As[(ak[q] + 3) * XSA + am[q]] = av[q].w;
            *(float4*)&Bs[br[q] * XSB + bc[q]] = bv[q];
        }
        __syncthreads();
        if (kt + 1 < F / 16) gload(kt + 1);

        #pragma unroll
        for (int ks = 0; ks < 2; ks++) {
            int kb = ks * 8;
            uint32_t af[2][4], bf[8][2];
            #pragma unroll
            for (int mt = 0; mt < 2; mt++) {
                int m = wm * 32 + mt * 16 + g;
                af[mt][0] = f2tf(As[(kb + tg) * XSA + m]);
                af[mt][1] = f2tf(As[(kb + tg) * XSA + m + 8]);
                af[mt][2] = f2tf(As[(kb + tg + 4) * XSA + m]);
                af[mt][3] = f2tf(As[(kb + tg + 4) * XSA + m + 8]);
            }
            #pragma unroll
            for (int nt = 0; nt < 8; nt++) {
                int n = wn * 64 + nt * 8 + g;
                bf[nt][0] = f2tf(Bs[(kb + tg) * XSB + n]);
                bf[nt][1] = f2tf(Bs[(kb + tg + 4) * XSB + n]);
            }
            #pragma unroll
            for (int mt = 0; mt < 2; mt++)
                #pragma unroll
                for (int nt = 0; nt < 8; nt++)
                    mma_tf32(acc[mt][nt], af[mt], bf[nt]);
        }
    }

    #pragma unroll
    for (int mt = 0; mt < 2; mt++) {
        int r0 = mBase + wm * 32 + mt * 16 + g;
        float d0 = g_dinv[r0], d1 = g_dinv[r0 + 8];
        #pragma unroll
        for (int nt = 0; nt < 8; nt++) {
            int c = nBase + wn * 64 + nt * 8 + tg * 2;
            float2 o0, o1;
            o0.x = __uint_as_float(f2tf(d0 * acc[mt][nt][0]));
            o0.y = __uint_as_float(f2tf(d0 * acc[mt][nt][1]));
            o1.x = __uint_as_float(f2tf(d1 * acc[mt][nt][2]));
            o1.y = __uint_as_float(f2tf(d1 * acc[mt][nt][3]));
            *(float2*)&g_hs[(size_t)r0 * F + c] = o0;
            *(float2*)&g_hs[(size_t)(r0 + 8) * F + c] = o1;
        }
    }
}

// ------------------------- kernel 4: aggregation ----------------------------
// y[i,f] = dinv[i] * sum_j G[j,i]*hs[j,f] + bias[f]
// BM=128 BN=256 BK=16, 256 threads (8 warps 2x4), warp tile 64x64.
// 4-stage cp.async pipeline; hs is pre-rounded tf32 (no CVT on B path).
#define ASA 136
#define ASB 264
#define A_FLOATS (16 * ASA)              // 2176
#define STG_FLOATS (16 * ASA + 16 * ASB) // 6400
#define STAGES 4
#define KT (NN / 16)                     // 512

__global__ __launch_bounds__(256, 1) void agg_tc(const float* __restrict__ graph,
                                                 const float* __restrict__ bias,
                                                 float* __restrict__ y) {
    extern __shared__ float dsm[];
    uint32_t sbase = smem_u32(dsm);

    int tid = threadIdx.x;
    int wid = tid >> 5, lane = tid & 31;
    int g = lane >> 2, tg = lane & 3;
    int wm = wid >> 2, wn = wid & 3;     // 2x4 warps, warp tile 64(M) x 64(N)
    int iBase = blockIdx.y * 128;
    int fBase = blockIdx.x * 256;

    // load maps: A 16x32 f4-chunks (2/thread), B 16x64 f4 (4/thread)
    int a_r[2], a_c[2], b_r[4], b_c[4];
    #pragma unroll
    for (int q = 0; q < 2; q++) {
        int id = tid + 256 * q;
        a_r[q] = id >> 5; a_c[q] = (id & 31) * 4;
    }
    #pragma unroll
    for (int q = 0; q < 4; q++) {
        int id = tid + 256 * q;
        b_r[q] = id >> 6; b_c[q] = (id & 63) * 4;
    }

    const float* gA = graph + iBase;            // + j*NN + i
    const float* hB = g_hs + fBase;             // + j*F + f

    auto load_stage = [&](int it) {
        uint32_t sb = sbase + (uint32_t)(it & (STAGES - 1)) * (STG_FLOATS * 4);
        int k0 = it * 16;
        #pragma unroll
        for (int q = 0; q < 2; q++)
            cpa16(sb + (uint32_t)(a_r[q] * ASA + a_c[q]) * 4,
                  gA + (size_t)(k0 + a_r[q]) * NN + a_c[q]);
        #pragma unroll
        for (int q = 0; q < 4; q++)
            cpa16(sb + (uint32_t)(A_FLOATS + b_r[q] * ASB + b_c[q]) * 4,
                  hB + (size_t)(k0 + b_r[q]) * F + b_c[q]);
    };

    float acc[4][8][4] = {};

    load_stage(0);
    asm volatile("cp.async.commit_group;" ::: "memory");
    load_stage(1);
    asm volatile("cp.async.commit_group;" ::: "memory");
    load_stage(2);
    asm volatile("cp.async.commit_group;" ::: "memory");

    for (int it = 0; it < KT; it++) {
        asm volatile("cp.async.wait_group 2;" ::: "memory");
        __syncthreads();

        const float* As = dsm + (it & (STAGES - 1)) * STG_FLOATS;
        const float* Bs = As + A_FLOATS;

        #pragma unroll
        for (int ks = 0; ks < 2; ks++) {
            int kb = ks * 8;
            uint32_t af[4][4], bf[8][2];
            #pragma unroll
            for (int mt = 0; mt < 4; mt++) {
                int m = wm * 64 + mt * 16 + g;
                af[mt][0] = f2tf(As[(kb + tg) * ASA + m]);
                af[mt][1] = f2tf(As[(kb + tg) * ASA + m + 8]);
                af[mt][2] = f2tf(As[(kb + tg + 4) * ASA + m]);
                af[mt][3] = f2tf(As[(kb + tg + 4) * ASA + m + 8]);
            }
            #pragma unroll
            for (int nt = 0; nt < 8; nt++) {
                int n = wn * 64 + nt * 8 + g;
                bf[nt][0] = __float_as_uint(Bs[(kb + tg) * ASB + n]);      // pre-rounded
                bf[nt][1] = __float_as_uint(Bs[(kb + tg + 4) * ASB + n]);
            }
            #pragma unroll
            for (int mt = 0; mt < 4; mt++)
                #pragma unroll
                for (int nt = 0; nt < 8; nt++)
                    mma_tf32(acc[mt][nt], af[mt], bf[nt]);
        }

        if (it + 3 < KT) {
            load_stage(it + 3);
        }
        asm volatile("cp.async.commit_group;" ::: "memory");
    }

    // epilogue
    #pragma unroll
    for (int mt = 0; mt < 4; mt++) {
        int r0 = iBase + wm * 64 + mt * 16 + g;
        float d0 = g_dinv[r0], d1 = g_dinv[r0 + 8];
        #pragma unroll
        for (int nt = 0; nt < 8; nt++) {
            int c = fBase + wn * 64 + nt * 8 + tg * 2;
            float2 bb = *(const float2*)&bias[c];
            float2 o0, o1;
            o0.x = fmaf(d0, acc[mt][nt][0], bb.x);
            o0.y = fmaf(d0, acc[mt][nt][1], bb.y);
            o1.x = fmaf(d1, acc[mt][nt][2], bb.x);
            o1.y = fmaf(d1, acc[mt][nt][3], bb.y);
            *(float2*)&y[(size_t)r0 * F + c] = o0;
            *(float2*)&y[(size_t)(r0 + 8) * F + c] = o1;
        }
    }
}

// ---------------------------------------------------------------------------
extern "C" void kernel_launch(void* const* d_in, const int* in_sizes, int n_in,
                              void* d_out, int out_size) {
    const float* x      = (const float*)d_in[0];  // [8192, 512]
    const float* graph  = (const float*)d_in[1];  // [8192, 8192]
    const float* weight = (const float*)d_in[2];  // [512, 512]
    const float* bias   = (const float*)d_in[3];  // [512]
    float* y = (float*)d_out;                     // [8192, 512]

    cudaFuncSetAttribute(agg_tc, cudaFuncAttributeMaxDynamicSharedMemorySize,
                         STAGES * STG_FLOATS * 4);

    zero_deg_kernel<<<NN / 256, 256>>>();
    deg_kernel<<<dim3(8, 64), 256>>>(graph);
    dinv_kernel<<<NN / 256, 256>>>();
    xw_tc<<<dim3(F / 128, NN / 128), 256>>>(x, weight);
    agg_tc<<<dim3(F / 256, NN / 128), 256, STAGES * STG_FLOATS * 4>>>(graph, bias, y);
}

// round 5
// speedup vs baseline: 5.0695x; 1.0670x over previous
#include <cuda_runtime.h>
#include <cstdint>

#define NN 8192
#define F  512

// ------------------------- device scratch (no allocs allowed) ---------------
__device__ float g_deg[NN];
__device__ float g_dinv[NN];
__device__ float g_hs[(size_t)NN * F];   // dinv[m]*(XW)[m,f], tf32-rounded bits

// ------------------------- helpers ------------------------------------------
__device__ __forceinline__ uint32_t smem_u32(const void* p) {
    uint32_t a;
    asm("{ .reg .u64 t; cvta.to.shared.u64 t, %1; cvt.u32.u64 %0, t; }"
        : "=r"(a) : "l"(p));
    return a;
}
__device__ __forceinline__ uint32_t f2tf(float x) {   // unbiased f32 -> tf32
    uint32_t r;
    asm("cvt.rna.tf32.f32 %0, %1;" : "=r"(r) : "f"(x));
    return r;
}
__device__ __forceinline__ void mma_tf32(float* c, const uint32_t* a, const uint32_t* b) {
    asm volatile(
        "mma.sync.aligned.m16n8k8.row.col.f32.tf32.tf32.f32 "
        "{%0,%1,%2,%3}, {%4,%5,%6,%7}, {%8,%9}, {%0,%1,%2,%3};"
        : "+f"(c[0]), "+f"(c[1]), "+f"(c[2]), "+f"(c[3])
        : "r"(a[0]), "r"(a[1]), "r"(a[2]), "r"(a[3]), "r"(b[0]), "r"(b[1]));
}
__device__ __forceinline__ void cpa16(uint32_t dst, const void* src) {
    asm volatile("cp.async.cg.shared.global [%0], [%1], 16;" :: "r"(dst), "l"(src));
}

// ------------------------- degree pipeline ----------------------------------
__global__ void zero_deg_kernel() {
    g_deg[blockIdx.x * 256 + threadIdx.x] = 0.f;
}

__global__ __launch_bounds__(256) void deg_kernel(const float* __restrict__ g) {
    int i4 = blockIdx.x * 1024 + threadIdx.x * 4;   // grid.x = 8
    int j0 = blockIdx.y * 128;                      // grid.y = 64
    float s0 = 0.f, s1 = 0.f, s2 = 0.f, s3 = 0.f;
    #pragma unroll 4
    for (int j = 0; j < 128; j++) {
        float4 v = *(const float4*)&g[(size_t)(j0 + j) * NN + i4];
        s0 += v.x; s1 += v.y; s2 += v.z; s3 += v.w;
    }
    atomicAdd(&g_deg[i4 + 0], s0);
    atomicAdd(&g_deg[i4 + 1], s1);
    atomicAdd(&g_deg[i4 + 2], s2);
    atomicAdd(&g_deg[i4 + 3], s3);
}

__global__ void dinv_kernel() {
    int i = blockIdx.x * 256 + threadIdx.x;
    g_dinv[i] = rsqrtf(g_deg[i]);
}

// ------------------------- kernel 3: hs = diag(dinv) * (X @ W) --------------
#define XSA 136
#define XSB 136
__global__ __launch_bounds__(256) void xw_tc(const float* __restrict__ x,
                                             const float* __restrict__ w) {
    __shared__ float As[16 * XSA];   // [k][m]
    __shared__ float Bs[16 * XSB];   // [k][n]

    int tid = threadIdx.x;
    int wid = tid >> 5, lane = tid & 31;
    int g = lane >> 2, tg = lane & 3;
    int wm = wid >> 1, wn = wid & 1;
    int mBase = blockIdx.y * 128;
    int nBase = blockIdx.x * 128;

    float acc[2][8][4] = {};
    float4 av[2], bv[2];
    int am[2], ak[2], br[2], bc[2];
    #pragma unroll
    for (int q = 0; q < 2; q++) {
        int id = tid + 256 * q;
        am[q] = id >> 2; ak[q] = (id & 3) * 4;
        br[q] = id >> 5; bc[q] = (id & 31) * 4;
    }

    auto gload = [&](int kt) {
        int k0 = kt * 16;
        #pragma unroll
        for (int q = 0; q < 2; q++) {
            av[q] = *(const float4*)&x[(size_t)(mBase + am[q]) * F + k0 + ak[q]];
            bv[q] = *(const float4*)&w[(size_t)(k0 + br[q]) * F + nBase + bc[q]];
        }
    };

    gload(0);
    for (int kt = 0; kt < F / 16; kt++) {
        __syncthreads();
        #pragma unroll
        for (int q = 0; q < 2; q++) {
            As[(ak[q] + 0) * XSA + am[q]] = av[q].x;
            As[(ak[q] + 1) * XSA + am[q]] = av[q].y;
            As[(ak[q] + 2) * XSA + am[q]] = av[q].z;
            As[(ak[q] + 3) * XSA + am[q]] = av[q].w;
            *(float4*)&Bs[br[q] * XSB + bc[q]] = bv[q];
        }
        __syncthreads();
        if (kt + 1 < F / 16) gload(kt + 1);

        #pragma unroll
        for (int ks = 0; ks < 2; ks++) {
            int kb = ks * 8;
            uint32_t af[2][4], bf[8][2];
            #pragma unroll
            for (int mt = 0; mt < 2; mt++) {
                int m = wm * 32 + mt * 16 + g;
                af[mt][0] = f2tf(As[(kb + tg) * XSA + m]);
                af[mt][1] = f2tf(As[(kb + tg) * XSA + m + 8]);
                af[mt][2] = f2tf(As[(kb + tg + 4) * XSA + m]);
                af[mt][3] = f2tf(As[(kb + tg + 4) * XSA + m + 8]);
            }
            #pragma unroll
            for (int nt = 0; nt < 8; nt++) {
                int n = wn * 64 + nt * 8 + g;
                bf[nt][0] = f2tf(Bs[(kb + tg) * XSB + n]);
                bf[nt][1] = f2tf(Bs[(kb + tg + 4) * XSB + n]);
            }
            #pragma unroll
            for (int mt = 0; mt < 2; mt++)
                #pragma unroll
                for (int nt = 0; nt < 8; nt++)
                    mma_tf32(acc[mt][nt], af[mt], bf[nt]);
        }
    }

    #pragma unroll
    for (int mt = 0; mt < 2; mt++) {
        int r0 = mBase + wm * 32 + mt * 16 + g;
        float d0 = g_dinv[r0], d1 = g_dinv[r0 + 8];
        #pragma unroll
        for (int nt = 0; nt < 8; nt++) {
            int c = nBase + wn * 64 + nt * 8 + tg * 2;
            float2 o0, o1;
            o0.x = __uint_as_float(f2tf(d0 * acc[mt][nt][0]));
            o0.y = __uint_as_float(f2tf(d0 * acc[mt][nt][1]));
            o1.x = __uint_as_float(f2tf(d1 * acc[mt][nt][2]));
            o1.y = __uint_as_float(f2tf(d1 * acc[mt][nt][3]));
            *(float2*)&g_hs[(size_t)r0 * F + c] = o0;
            *(float2*)&g_hs[(size_t)(r0 + 8) * F + c] = o1;
        }
    }
}

// ------------------------- kernel 4: aggregation ----------------------------
// y[i,f] = dinv[i] * sum_j G[j,i]*hs[j,f] + bias[f]
// BM=128 BN=256 BK=32, 256 threads (8 warps 2x4), warp tile 64x64.
// 3-stage cp.async; A fed as raw fp32 bits (tf32 truncation), B pre-rounded.
#define BKA 32
#define ASA 136
#define ASB 264
#define A_FLOATS (BKA * ASA)               // 4352
#define STG_FLOATS (BKA * (ASA + ASB))     // 12800
#define STAGES 3
#define KT (NN / BKA)                      // 256

__global__ __launch_bounds__(256, 1) void agg_tc(const float* __restrict__ graph,
                                                 const float* __restrict__ bias,
                                                 float* __restrict__ y) {
    extern __shared__ float dsm[];

    int tid = threadIdx.x;
    int wid = tid >> 5, lane = tid & 31;
    int g = lane >> 2, tg = lane & 3;
    int wm = wid >> 2, wn = wid & 3;     // 2x4 warps, warp tile 64(M) x 64(N)
    int iBase = blockIdx.y * 128;
    int fBase = blockIdx.x * 256;

    uint32_t sbase = smem_u32(dsm);

    // load maps: A 32x32 f4-chunks (4/thread), B 32x64 f4 (8/thread)
    int a_r[4], a_c[4], b_r[8], b_c[8];
    #pragma unroll
    for (int q = 0; q < 4; q++) {
        int id = tid + 256 * q;
        a_r[q] = id >> 5; a_c[q] = (id & 31) * 4;
    }
    #pragma unroll
    for (int q = 0; q < 8; q++) {
        int id = tid + 256 * q;
        b_r[q] = id >> 6; b_c[q] = (id & 63) * 4;
    }

    const float* gA = graph + iBase;            // + j*NN + i
    const float* hB = g_hs + fBase;             // + j*F + f

    auto load_stage = [&](int it) {
        uint32_t sb = sbase + (uint32_t)(it % STAGES) * (STG_FLOATS * 4);
        int k0 = it * BKA;
        #pragma unroll
        for (int q = 0; q < 4; q++)
            cpa16(sb + (uint32_t)(a_r[q] * ASA + a_c[q]) * 4,
                  gA + (size_t)(k0 + a_r[q]) * NN + a_c[q]);
        #pragma unroll
        for (int q = 0; q < 8; q++)
            cpa16(sb + (uint32_t)(A_FLOATS + b_r[q] * ASB + b_c[q]) * 4,
                  hB + (size_t)(k0 + b_r[q]) * F + b_c[q]);
    };

    float acc[4][8][4] = {};

    load_stage(0);
    asm volatile("cp.async.commit_group;" ::: "memory");
    load_stage(1);
    asm volatile("cp.async.commit_group;" ::: "memory");

    for (int it = 0; it < KT; it++) {
        asm volatile("cp.async.wait_group 1;" ::: "memory");
        __syncthreads();

        const float* As = dsm + (it % STAGES) * STG_FLOATS;
        const float* Bs = As + A_FLOATS;

        #pragma unroll
        for (int ks = 0; ks < 4; ks++) {
            int kb = ks * 8;
            uint32_t af[4][4], bf[8][2];
            #pragma unroll
            for (int mt = 0; mt < 4; mt++) {
                int m = wm * 64 + mt * 16 + g;
                af[mt][0] = __float_as_uint(As[(kb + tg) * ASA + m]);
                af[mt][1] = __float_as_uint(As[(kb + tg) * ASA + m + 8]);
                af[mt][2] = __float_as_uint(As[(kb + tg + 4) * ASA + m]);
                af[mt][3] = __float_as_uint(As[(kb + tg + 4) * ASA + m + 8]);
            }
            #pragma unroll
            for (int nt = 0; nt < 8; nt++) {
                int n = wn * 64 + nt * 8 + g;
                bf[nt][0] = __float_as_uint(Bs[(kb + tg) * ASB + n]);
                bf[nt][1] = __float_as_uint(Bs[(kb + tg + 4) * ASB + n]);
            }
            #pragma unroll
            for (int mt = 0; mt < 4; mt++)
                #pragma unroll
                for (int nt = 0; nt < 8; nt++)
                    mma_tf32(acc[mt][nt], af[mt], bf[nt]);
        }

        if (it + 2 < KT) load_stage(it + 2);
        asm volatile("cp.async.commit_group;" ::: "memory");
    }

    // epilogue
    #pragma unroll
    for (int mt = 0; mt < 4; mt++) {
        int r0 = iBase + wm * 64 + mt * 16 + g;
        float d0 = g_dinv[r0], d1 = g_dinv[r0 + 8];
        #pragma unroll
        for (int nt = 0; nt < 8; nt++) {
            int c = fBase + wn * 64 + nt * 8 + tg * 2;
            float2 bb = *(const float2*)&bias[c];
            float2 o0, o1;
            o0.x = fmaf(d0, acc[mt][nt][0], bb.x);
            o0.y = fmaf(d0, acc[mt][nt][1], bb.y);
            o1.x = fmaf(d1, acc[mt][nt][2], bb.x);
            o1.y = fmaf(d1, acc[mt][nt][3], bb.y);
            *(float2*)&y[(size_t)r0 * F + c] = o0;
            *(float2*)&y[(size_t)(r0 + 8) * F + c] = o1;
        }
    }
}

// ---------------------------------------------------------------------------
extern "C" void kernel_launch(void* const* d_in, const int* in_sizes, int n_in,
                              void* d_out, int out_size) {
    const float* x      = (const float*)d_in[0];  // [8192, 512]
    const float* graph  = (const float*)d_in[1];  // [8192, 8192]
    const float* weight = (const float*)d_in[2];  // [512, 512]
    const float* bias   = (const float*)d_in[3];  // [512]
    float* y = (float*)d_out;                     // [8192, 512]

    cudaFuncSetAttribute(agg_tc, cudaFuncAttributeMaxDynamicSharedMemorySize,
                         STAGES * STG_FLOATS * 4);

    zero_deg_kernel<<<NN / 256, 256>>>();
    deg_kernel<<<dim3(8, 64), 256>>>(graph);
    dinv_kernel<<<NN / 256, 256>>>();
    xw_tc<<<dim3(F / 128, NN / 128), 256>>>(x, weight);
    agg_tc<<<dim3(F / 256, NN / 128), 256, STAGES * STG_FLOATS * 4>>>(graph, bias, y);
}

// round 6
// speedup vs baseline: 6.7356x; 1.3287x over previous
#include <cuda_runtime.h>
#include <cuda_fp16.h>
#include <cstdint>

#define NN 8192
#define F  512

// ------------------------- device scratch (no allocs allowed) ---------------
__device__ float  g_deg[NN];
__device__ float  g_dinv[NN];
__device__ __half g_gh[(size_t)NN * NN];   // fp16(graph), same [j][i] layout, 128 MB
__device__ __half g_hs[(size_t)NN * F];    // fp16( dinv[m]*(XW)[m,f] ), 8 MB

// ------------------------- helpers ------------------------------------------
__device__ __forceinline__ uint32_t smem_u32(const void* p) {
    uint32_t a;
    asm("{ .reg .u64 t; cvta.to.shared.u64 t, %1; cvt.u32.u64 %0, t; }"
        : "=r"(a) : "l"(p));
    return a;
}
__device__ __forceinline__ uint32_t f2tf(float x) {
    uint32_t r;
    asm("cvt.rna.tf32.f32 %0, %1;" : "=r"(r) : "f"(x));
    return r;
}
__device__ __forceinline__ void mma_tf32(float* c, const uint32_t* a, const uint32_t* b) {
    asm volatile(
        "mma.sync.aligned.m16n8k8.row.col.f32.tf32.tf32.f32 "
        "{%0,%1,%2,%3}, {%4,%5,%6,%7}, {%8,%9}, {%0,%1,%2,%3};"
        : "+f"(c[0]), "+f"(c[1]), "+f"(c[2]), "+f"(c[3])
        : "r"(a[0]), "r"(a[1]), "r"(a[2]), "r"(a[3]), "r"(b[0]), "r"(b[1]));
}
__device__ __forceinline__ void mma_f16(float* c, const uint32_t* a, const uint32_t* b) {
    asm volatile(
        "mma.sync.aligned.m16n8k16.row.col.f32.f16.f16.f32 "
        "{%0,%1,%2,%3}, {%4,%5,%6,%7}, {%8,%9}, {%0,%1,%2,%3};"
        : "+f"(c[0]), "+f"(c[1]), "+f"(c[2]), "+f"(c[3])
        : "r"(a[0]), "r"(a[1]), "r"(a[2]), "r"(a[3]), "r"(b[0]), "r"(b[1]));
}
__device__ __forceinline__ void ldsm4t(uint32_t* r, uint32_t addr) {
    asm volatile("ldmatrix.sync.aligned.m8n8.x4.trans.shared.b16 {%0,%1,%2,%3}, [%4];"
                 : "=r"(r[0]), "=r"(r[1]), "=r"(r[2]), "=r"(r[3]) : "r"(addr));
}
__device__ __forceinline__ void cpa16(uint32_t dst, const void* src) {
    asm volatile("cp.async.cg.shared.global [%0], [%1], 16;" :: "r"(dst), "l"(src));
}

// ------------------------- degree + fp16 convert -----------------------------
__global__ void zero_deg_kernel() {
    g_deg[blockIdx.x * 256 + threadIdx.x] = 0.f;
}

// deg[i] += sum over j-slab of graph[j][i]; also writes g_gh = fp16(graph).
__global__ __launch_bounds__(256) void deg_cvt_kernel(const float* __restrict__ g) {
    int i4 = blockIdx.x * 1024 + threadIdx.x * 4;   // grid.x = 8
    int j0 = blockIdx.y * 128;                      // grid.y = 64
    float s0 = 0.f, s1 = 0.f, s2 = 0.f, s3 = 0.f;
    #pragma unroll 4
    for (int j = 0; j < 128; j++) {
        size_t off = (size_t)(j0 + j) * NN + i4;
        float4 v = *(const float4*)&g[off];
        s0 += v.x; s1 += v.y; s2 += v.z; s3 += v.w;
        __half2 h01 = __floats2half2_rn(v.x, v.y);
        __half2 h23 = __floats2half2_rn(v.z, v.w);
        uint2 u;
        u.x = *(uint32_t*)&h01;
        u.y = *(uint32_t*)&h23;
        *(uint2*)&g_gh[off] = u;
    }
    atomicAdd(&g_deg[i4 + 0], s0);
    atomicAdd(&g_deg[i4 + 1], s1);
    atomicAdd(&g_deg[i4 + 2], s2);
    atomicAdd(&g_deg[i4 + 3], s3);
}

__global__ void dinv_kernel() {
    int i = blockIdx.x * 256 + threadIdx.x;
    g_dinv[i] = rsqrtf(g_deg[i]);
}

// ------------------------- kernel 3: hs = fp16( diag(dinv) * (X @ W) ) ------
#define XSA 136
#define XSB 136
__global__ __launch_bounds__(256) void xw_tc(const float* __restrict__ x,
                                             const float* __restrict__ w) {
    __shared__ float As[16 * XSA];   // [k][m]
    __shared__ float Bs[16 * XSB];   // [k][n]

    int tid = threadIdx.x;
    int wid = tid >> 5, lane = tid & 31;
    int g = lane >> 2, tg = lane & 3;
    int wm = wid >> 1, wn = wid & 1;
    int mBase = blockIdx.y * 128;
    int nBase = blockIdx.x * 128;

    float acc[2][8][4] = {};
    float4 av[2], bv[2];
    int am[2], ak[2], br[2], bc[2];
    #pragma unroll
    for (int q = 0; q < 2; q++) {
        int id = tid + 256 * q;
        am[q] = id >> 2; ak[q] = (id & 3) * 4;
        br[q] = id >> 5; bc[q] = (id & 31) * 4;
    }

    auto gload = [&](int kt) {
        int k0 = kt * 16;
        #pragma unroll
        for (int q = 0; q < 2; q++) {
            av[q] = *(const float4*)&x[(size_t)(mBase + am[q]) * F + k0 + ak[q]];
            bv[q] = *(const float4*)&w[(size_t)(k0 + br[q]) * F + nBase + bc[q]];
        }
    };

    gload(0);
    for (int kt = 0; kt < F / 16; kt++) {
        __syncthreads();
        #pragma unroll
        for (int q = 0; q < 2; q++) {
            As[(ak[q] + 0) * XSA + am[q]] = av[q].x;
            As[(ak[q] + 1) * XSA + am[q]] = av[q].y;
            As[(ak[q] + 2) * XSA + am[q]] = av[q].z;
            As[(ak[q] + 3) * XSA + am[q]] = av[q].w;
            *(float4*)&Bs[br[q] * XSB + bc[q]] = bv[q];
        }
        __syncthreads();
        if (kt + 1 < F / 16) gload(kt + 1);

        #pragma unroll
        for (int ks = 0; ks < 2; ks++) {
            int kb = ks * 8;
            uint32_t af[2][4], bf[8][2];
            #pragma unroll
            for (int mt = 0; mt < 2; mt++) {
                int m = wm * 32 + mt * 16 + g;
                af[mt][0] = f2tf(As[(kb + tg) * XSA + m]);
                af[mt][1] = f2tf(As[(kb + tg) * XSA + m + 8]);
                af[mt][2] = f2tf(As[(kb + tg + 4) * XSA + m]);
                af[mt][3] = f2tf(As[(kb + tg + 4) * XSA + m + 8]);
            }
            #pragma unroll
            for (int nt = 0; nt < 8; nt++) {
                int n = wn * 64 + nt * 8 + g;
                bf[nt][0] = f2tf(Bs[(kb + tg) * XSB + n]);
                bf[nt][1] = f2tf(Bs[(kb + tg + 4) * XSB + n]);
            }
            #pragma unroll
            for (int mt = 0; mt < 2; mt++)
                #pragma unroll
                for (int nt = 0; nt < 8; nt++)
                    mma_tf32(acc[mt][nt], af[mt], bf[nt]);
        }
    }

    #pragma unroll
    for (int mt = 0; mt < 2; mt++) {
        int r0 = mBase + wm * 32 + mt * 16 + g;
        float d0 = g_dinv[r0], d1 = g_dinv[r0 + 8];
        #pragma unroll
        for (int nt = 0; nt < 8; nt++) {
            int c = nBase + wn * 64 + nt * 8 + tg * 2;
            __half2 h0 = __floats2half2_rn(d0 * acc[mt][nt][0], d0 * acc[mt][nt][1]);
            __half2 h1 = __floats2half2_rn(d1 * acc[mt][nt][2], d1 * acc[mt][nt][3]);
            *(__half2*)&g_hs[(size_t)r0 * F + c] = h0;
            *(__half2*)&g_hs[(size_t)(r0 + 8) * F + c] = h1;
        }
    }
}

// ------------------------- kernel 4: fp16 aggregation -----------------------
// y[i,f] = dinv[i] * sum_j Gh[j,i]*hs[j,f] + bias[f]
// BM=128 BN=256 BK=32, 256 thr (8 warps 2x4), warp tile 64x64.
// fp16 operands via ldmatrix.x4.trans, fp32 accum. 4-stage cp.async.
#define BKA 32
#define ASA 136                               // fp16 elems per A row (pad 128->136)
#define ASB 264                               // fp16 elems per B row (pad 256->264)
#define A_BYTES (BKA * ASA * 2)               // 8704
#define STG_BYTES (BKA * (ASA + ASB) * 2)     // 25600
#define STAGES 4
#define KT (NN / BKA)                         // 256

__global__ __launch_bounds__(256, 1) void agg_f16(const float* __restrict__ bias,
                                                  float* __restrict__ y) {
    extern __shared__ __half hsm[];
    uint32_t sbase = smem_u32(hsm);

    int tid = threadIdx.x;
    int wid = tid >> 5, lane = tid & 31;
    int g = lane >> 2, tg = lane & 3;
    int wm = wid >> 2, wn = wid & 3;     // 2x4 warps, warp tile 64(M) x 64(N)
    int iBase = blockIdx.y * 128;
    int fBase = blockIdx.x * 256;

    // ldmatrix lane geometry
    int grp = lane >> 3, lrow = lane & 7;
    int gk = (grp >> 1) * 8 + lrow;      // k offset within 16x16 tile pattern
    int gm = (grp & 1) * 8;              // m/n offset

    // cp.async maps: A rows 32 x 16 chunks (2/thr), B rows 32 x 32 chunks (4/thr)
    int a_r[2], a_c[2], b_r[4], b_c[4];
    #pragma unroll
    for (int q = 0; q < 2; q++) {
        int id = tid + 256 * q;
        a_r[q] = id >> 4; a_c[q] = (id & 15) * 8;
    }
    #pragma unroll
    for (int q = 0; q < 4; q++) {
        int id = tid + 256 * q;
        b_r[q] = id >> 5; b_c[q] = (id & 31) * 8;
    }

    const __half* gA = g_gh + iBase;          // + j*NN + i
    const __half* hB = g_hs + fBase;          // + j*F + f

    auto load_stage = [&](int it) {
        uint32_t sb = sbase + (uint32_t)(it & (STAGES - 1)) * STG_BYTES;
        int k0 = it * BKA;
        #pragma unroll
        for (int q = 0; q < 2; q++)
            cpa16(sb + (uint32_t)(a_r[q] * ASA + a_c[q]) * 2,
                  gA + (size_t)(k0 + a_r[q]) * NN + a_c[q]);
        #pragma unroll
        for (int q = 0; q < 4; q++)
            cpa16(sb + A_BYTES + (uint32_t)(b_r[q] * ASB + b_c[q]) * 2,
                  hB + (size_t)(k0 + b_r[q]) * F + b_c[q]);
    };

    float acc[4][8][4] = {};

    load_stage(0);
    asm volatile("cp.async.commit_group;" ::: "memory");
    load_stage(1);
    asm volatile("cp.async.commit_group;" ::: "memory");
    load_stage(2);
    asm volatile("cp.async.commit_group;" ::: "memory");

    for (int it = 0; it < KT; it++) {
        asm volatile("cp.async.wait_group 2;" ::: "memory");
        __syncthreads();

        uint32_t sA = sbase + (uint32_t)(it & (STAGES - 1)) * STG_BYTES;
        uint32_t sB = sA + A_BYTES;

        #pragma unroll
        for (int ks = 0; ks < 2; ks++) {
            int kb = ks * 16;
            uint32_t af[4][4], bf[8][2];
            #pragma unroll
            for (int mt = 0; mt < 4; mt++) {
                uint32_t addr = sA + (uint32_t)((kb + gk) * ASA + wm * 64 + mt * 16 + gm) * 2;
                ldsm4t(af[mt], addr);
            }
            #pragma unroll
            for (int p = 0; p < 4; p++) {
                uint32_t r[4];
                uint32_t addr = sB + (uint32_t)((kb + gk) * ASB + wn * 64 + p * 16 + gm) * 2;
                ldsm4t(r, addr);
                bf[2 * p][0] = r[0]; bf[2 * p + 1][0] = r[1];
                bf[2 * p][1] = r[2]; bf[2 * p + 1][1] = r[3];
            }
            #pragma unroll
            for (int mt = 0; mt < 4; mt++)
                #pragma unroll
                for (int nt = 0; nt < 8; nt++)
                    mma_f16(acc[mt][nt], af[mt], bf[nt]);
        }

        if (it + 3 < KT) load_stage(it + 3);
        asm volatile("cp.async.commit_group;" ::: "memory");
    }

    // epilogue (same accumulator layout as m16n8k8)
    #pragma unroll
    for (int mt = 0; mt < 4; mt++) {
        int r0 = iBase + wm * 64 + mt * 16 + g;
        float d0 = g_dinv[r0], d1 = g_dinv[r0 + 8];
        #pragma unroll
        for (int nt = 0; nt < 8; nt++) {
            int c = fBase + wn * 64 + nt * 8 + tg * 2;
            float2 bb = *(const float2*)&bias[c];
            float2 o0, o1;
            o0.x = fmaf(d0, acc[mt][nt][0], bb.x);
            o0.y = fmaf(d0, acc[mt][nt][1], bb.y);
            o1.x = fmaf(d1, acc[mt][nt][2], bb.x);
            o1.y = fmaf(d1, acc[mt][nt][3], bb.y);
            *(float2*)&y[(size_t)r0 * F + c] = o0;
            *(float2*)&y[(size_t)(r0 + 8) * F + c] = o1;
        }
    }
}

// ---------------------------------------------------------------------------
extern "C" void kernel_launch(void* const* d_in, const int* in_sizes, int n_in,
                              void* d_out, int out_size) {
    const float* x      = (const float*)d_in[0];  // [8192, 512]
    const float* graph  = (const float*)d_in[1];  // [8192, 8192]
    const float* weight = (const float*)d_in[2];  // [512, 512]
    const float* bias   = (const float*)d_in[3];  // [512]
    float* y = (float*)d_out;                     // [8192, 512]

    cudaFuncSetAttribute(agg_f16, cudaFuncAttributeMaxDynamicSharedMemorySize,
                         STAGES * STG_BYTES);

    zero_deg_kernel<<<NN / 256, 256>>>();
    deg_cvt_kernel<<<dim3(8, 64), 256>>>(graph);
    dinv_kernel<<<NN / 256, 256>>>();
    xw_tc<<<dim3(F / 128, NN / 128), 256>>>(x, weight);
    agg_f16<<<dim3(F / 256, NN / 128), 256, STAGES * STG_BYTES>>>(bias, y);
}